// round 1
// baseline (speedup 1.0000x reference)
#include <cuda_runtime.h>
#include <cuda_bf16.h>

#define NN 100000
#define EE 300000
#define GG 4096
#define DD 256
#define LL 5
#define BN_EPS 1e-5f

// ---------------- scratch (device globals; no allocations) ----------------
__device__ float g_ea[(size_t)EE * DD];      // bond embeddings per edge
__device__ float g_agg[(size_t)NN * DD];     // edge aggregation
__device__ float g_t[(size_t)NN * DD];       // z / gemm2 out
__device__ float g_y[(size_t)NN * DD];       // gemm1 out
__device__ float g_vn[(size_t)GG * DD];      // virtual node state
__device__ float g_pooled[(size_t)GG * DD];
__device__ float g_vt[(size_t)GG * DD];
__device__ float g_vt2[(size_t)GG * DD];
__device__ float g_stats[2 * DD];            // column sum / sumsq

// ---------------- elementwise kernels ----------------
__global__ void k_zero(float* p, int n4) {  // n4 = count of float4
    int i = blockIdx.x * blockDim.x + threadIdx.x;
    if (i < n4) ((float4*)p)[i] = make_float4(0.f, 0.f, 0.f, 0.f);
}

__global__ void k_copy(float* dst, const float* src, int n4) {
    int i = blockIdx.x * blockDim.x + threadIdx.x;
    if (i < n4) ((float4*)dst)[i] = ((const float4*)src)[i];
}

__global__ void k_encode_atoms(const int* __restrict__ x,
                               const float* __restrict__ atom_emb,
                               float* __restrict__ out0) {
    int idx = blockIdx.x * blockDim.x + threadIdx.x;
    if (idx >= NN * 64) return;
    int n = idx >> 6;
    int d4 = (idx & 63) * 4;
    float4 acc = make_float4(0.f, 0.f, 0.f, 0.f);
#pragma unroll
    for (int f = 0; f < 9; f++) {
        int v = __ldg(&x[n * 9 + f]);
        float4 e = *(const float4*)(atom_emb + ((size_t)(f * 120 + v) * DD + d4));
        acc.x += e.x; acc.y += e.y; acc.z += e.z; acc.w += e.w;
    }
    *(float4*)(out0 + (size_t)n * DD + d4) = acc;
}

__global__ void k_encode_bonds(const int* __restrict__ ea_idx,
                               const float* __restrict__ bond_emb) {
    int idx = blockIdx.x * blockDim.x + threadIdx.x;
    if (idx >= EE * 64) return;
    int e = idx >> 6;
    int d4 = (idx & 63) * 4;
    float4 acc = make_float4(0.f, 0.f, 0.f, 0.f);
#pragma unroll
    for (int f = 0; f < 3; f++) {
        int v = __ldg(&ea_idx[e * 3 + f]);
        float4 em = *(const float4*)(bond_emb + ((size_t)(f * 6 + v) * DD + d4));
        acc.x += em.x; acc.y += em.y; acc.z += em.z; acc.w += em.w;
    }
    *(float4*)(g_ea + (size_t)e * DD + d4) = acc;
}

__global__ void k_vn_init(const float* __restrict__ vn_emb) {
    int i = blockIdx.x * blockDim.x + threadIdx.x;  // over GG*DD
    if (i < GG * DD) g_vn[i] = vn_emb[i & (DD - 1)];
}

__global__ void k_add_vn(float* __restrict__ h, const int* __restrict__ batch) {
    int idx = blockIdx.x * blockDim.x + threadIdx.x;
    if (idx >= NN * 64) return;
    int n = idx >> 6;
    int d4 = (idx & 63) * 4;
    int g = __ldg(&batch[n]);
    float4 v = *(float4*)(h + (size_t)n * DD + d4);
    float4 w = *(const float4*)(g_vn + (size_t)g * DD + d4);
    v.x += w.x; v.y += w.y; v.z += w.z; v.w += w.w;
    *(float4*)(h + (size_t)n * DD + d4) = v;
}

__global__ void k_edge_msg(const int* __restrict__ ei,
                           const float* __restrict__ h) {
    int idx = blockIdx.x * blockDim.x + threadIdx.x;
    if (idx >= EE * 64) return;
    int e = idx >> 6;
    int d4 = (idx & 63) * 4;
    int s = __ldg(&ei[e]);
    int t = __ldg(&ei[EE + e]);
    float4 hv = *(const float4*)(h + (size_t)s * DD + d4);
    float4 av = *(const float4*)(g_ea + (size_t)e * DD + d4);
    float m0 = fmaxf(hv.x + av.x, 0.f);
    float m1 = fmaxf(hv.y + av.y, 0.f);
    float m2 = fmaxf(hv.z + av.z, 0.f);
    float m3 = fmaxf(hv.w + av.w, 0.f);
    float* p = g_agg + (size_t)t * DD + d4;
    atomicAdd(p + 0, m0);
    atomicAdd(p + 1, m1);
    atomicAdd(p + 2, m2);
    atomicAdd(p + 3, m3);
}

__global__ void k_gin_combine(const float* __restrict__ h,
                              const float* __restrict__ eps_ptr) {
    int idx = blockIdx.x * blockDim.x + threadIdx.x;
    if (idx >= NN * 64) return;
    float e = 1.0f + __ldg(eps_ptr);
    int n = idx >> 6;
    int d4 = (idx & 63) * 4;
    float4 hv = *(const float4*)(h + (size_t)n * DD + d4);
    float4 av = *(const float4*)(g_agg + (size_t)n * DD + d4);
    float4 o;
    o.x = e * hv.x + av.x;
    o.y = e * hv.y + av.y;
    o.z = e * hv.z + av.z;
    o.w = e * hv.w + av.w;
    *(float4*)(g_t + (size_t)n * DD + d4) = o;
}

__global__ void k_pool_scatter(const float* __restrict__ h,
                               const int* __restrict__ batch) {
    int idx = blockIdx.x * blockDim.x + threadIdx.x;
    if (idx >= NN * 64) return;
    int n = idx >> 6;
    int d4 = (idx & 63) * 4;
    int g = __ldg(&batch[n]);
    float4 v = *(const float4*)(h + (size_t)n * DD + d4);
    float* p = g_pooled + (size_t)g * DD + d4;
    atomicAdd(p + 0, v.x);
    atomicAdd(p + 1, v.y);
    atomicAdd(p + 2, v.z);
    atomicAdd(p + 3, v.w);
}

// ---------------- GEMM: C[M,256] = A[M,256] @ W[256,256] + bias ----------------
#define BM 128
#define BNN 128
#define BK 16

__global__ void __launch_bounds__(256, 2)
k_gemm_bias(const float* __restrict__ A, const float* __restrict__ W,
            const float* __restrict__ bias, float* __restrict__ C, int M) {
    __shared__ float As[BK][BM];
    __shared__ float Ws[BK][BNN];
    int tid = threadIdx.x;
    int row0 = blockIdx.x * BM;
    int col0 = blockIdx.y * BNN;
    int tx = tid & 15;   // col group
    int ty = tid >> 4;   // row group
    float acc[8][8];
#pragma unroll
    for (int i = 0; i < 8; i++)
#pragma unroll
        for (int j = 0; j < 8; j++) acc[i][j] = 0.f;

    for (int k0 = 0; k0 < DD; k0 += BK) {
        // A tile: 128 rows x 16 cols (store transposed)
#pragma unroll
        for (int i = 0; i < 2; i++) {
            int li = tid + i * 256;     // 0..511 float4 ids
            int r = li >> 2;
            int c4 = (li & 3) * 4;
            float4 v = make_float4(0.f, 0.f, 0.f, 0.f);
            int gr = row0 + r;
            if (gr < M) v = *(const float4*)(A + (size_t)gr * DD + k0 + c4);
            As[c4 + 0][r] = v.x;
            As[c4 + 1][r] = v.y;
            As[c4 + 2][r] = v.z;
            As[c4 + 3][r] = v.w;
        }
        // W tile: 16 rows x 128 cols
#pragma unroll
        for (int i = 0; i < 2; i++) {
            int li = tid + i * 256;
            int r = li >> 5;
            int c4 = (li & 31) * 4;
            *(float4*)(&Ws[r][c4]) = *(const float4*)(W + (size_t)(k0 + r) * DD + col0 + c4);
        }
        __syncthreads();
#pragma unroll
        for (int k = 0; k < BK; k++) {
            float a[8], b[8];
            *(float4*)(&a[0]) = *(const float4*)(&As[k][ty * 8]);
            *(float4*)(&a[4]) = *(const float4*)(&As[k][ty * 8 + 4]);
            *(float4*)(&b[0]) = *(const float4*)(&Ws[k][tx * 8]);
            *(float4*)(&b[4]) = *(const float4*)(&Ws[k][tx * 8 + 4]);
#pragma unroll
            for (int i = 0; i < 8; i++)
#pragma unroll
                for (int j = 0; j < 8; j++) acc[i][j] += a[i] * b[j];
        }
        __syncthreads();
    }
#pragma unroll
    for (int i = 0; i < 8; i++) {
        int gr = row0 + ty * 8 + i;
        if (gr >= M) continue;
#pragma unroll
        for (int j = 0; j < 8; j += 4) {
            int gc = col0 + tx * 8 + j;
            float4 v;
            v.x = acc[i][j + 0] + __ldg(&bias[gc + 0]);
            v.y = acc[i][j + 1] + __ldg(&bias[gc + 1]);
            v.z = acc[i][j + 2] + __ldg(&bias[gc + 2]);
            v.w = acc[i][j + 3] + __ldg(&bias[gc + 3]);
            *(float4*)(C + (size_t)gr * DD + gc) = v;
        }
    }
}

// ---------------- BatchNorm (training-mode, batch stats) ----------------
__global__ void k_zero_stats() {
    int i = threadIdx.x;
    if (i < 2 * DD) g_stats[i] = 0.f;
}

__global__ void k_colstats(const float* __restrict__ Y, int M) {
    int col = threadIdx.x;  // 256 threads
    int rows_per = (M + gridDim.x - 1) / gridDim.x;
    int r0 = blockIdx.x * rows_per;
    int r1 = min(M, r0 + rows_per);
    float s = 0.f, s2 = 0.f;
    for (int r = r0; r < r1; r++) {
        float v = Y[(size_t)r * DD + col];
        s += v;
        s2 += v * v;
    }
    atomicAdd(&g_stats[col], s);
    atomicAdd(&g_stats[DD + col], s2);
}

__global__ void k_bn_apply(const float* __restrict__ Yin, float* __restrict__ Yout,
                           const float* __restrict__ gamma, const float* __restrict__ beta,
                           int M, int do_relu) {
    int idx = blockIdx.x * blockDim.x + threadIdx.x;
    if (idx >= M * 64) return;
    int r = idx >> 6;
    int c4 = (idx & 63) * 4;
    float inv = 1.0f / (float)M;
    float4 s = *(const float4*)(g_stats + c4);
    float4 s2 = *(const float4*)(g_stats + DD + c4);
    float4 g = *(const float4*)(gamma + c4);
    float4 b = *(const float4*)(beta + c4);
    float4 v = *(const float4*)(Yin + (size_t)r * DD + c4);
    float m, var, rs, o;
#define BN1(X)                                             \
    m = s.X * inv;                                         \
    var = s2.X * inv - m * m;                              \
    rs = rsqrtf(var + BN_EPS);                             \
    o = (v.X - m) * rs * g.X + b.X;                        \
    if (do_relu) o = fmaxf(o, 0.f);                        \
    v.X = o;
    BN1(x) BN1(y) BN1(z) BN1(w)
#undef BN1
    *(float4*)(Yout + (size_t)r * DD + c4) = v;
}

// ---------------- host orchestration ----------------
static inline void bn_pipeline(const float* Y, float* Yout, const float* gamma,
                               const float* beta, int M, int relu) {
    k_zero_stats<<<1, 512>>>();
    int nblk = (M >= 32768) ? 512 : 64;
    k_colstats<<<nblk, 256>>>(Y, M);
    k_bn_apply<<<(M * 64 + 255) / 256, 256>>>(Y, Yout, gamma, beta, M, relu);
}

extern "C" void kernel_launch(void* const* d_in, const int* in_sizes, int n_in,
                              void* d_out, int out_size) {
    const int* x          = (const int*)d_in[0];
    const int* edge_index = (const int*)d_in[1];
    const int* edge_attr  = (const int*)d_in[2];
    const int* batch      = (const int*)d_in[3];
    const float* atom_emb = (const float*)d_in[4];
    const float* bond_emb = (const float*)d_in[5];
    const float* vn_emb   = (const float*)d_in[6];
    const float* gin_eps  = (const float*)d_in[7];
    const float* conv_W1  = (const float*)d_in[8];
    const float* conv_b1  = (const float*)d_in[9];
    const float* conv_bn_g = (const float*)d_in[10];
    const float* conv_bn_b = (const float*)d_in[11];
    const float* conv_W2  = (const float*)d_in[12];
    const float* conv_b2  = (const float*)d_in[13];
    const float* outer_bn_g = (const float*)d_in[14];
    const float* outer_bn_b = (const float*)d_in[15];
    const float* vn_W1    = (const float*)d_in[16];
    const float* vn_b1    = (const float*)d_in[17];
    const float* vn_bn1_g = (const float*)d_in[18];
    const float* vn_bn1_b = (const float*)d_in[19];
    const float* vn_W2    = (const float*)d_in[20];
    const float* vn_b2    = (const float*)d_in[21];
    const float* vn_bn2_g = (const float*)d_in[22];
    const float* vn_bn2_b = (const float*)d_in[23];
    float* out = (float*)d_out;

    float *p_ea, *p_agg, *p_t, *p_y, *p_pooled, *p_vt, *p_vt2, *p_vn;
    cudaGetSymbolAddress((void**)&p_ea, g_ea);
    cudaGetSymbolAddress((void**)&p_agg, g_agg);
    cudaGetSymbolAddress((void**)&p_t, g_t);
    cudaGetSymbolAddress((void**)&p_y, g_y);
    cudaGetSymbolAddress((void**)&p_pooled, g_pooled);
    cudaGetSymbolAddress((void**)&p_vt, g_vt);
    cudaGetSymbolAddress((void**)&p_vt2, g_vt2);
    cudaGetSymbolAddress((void**)&p_vn, g_vn);

    const size_t slot = (size_t)NN * DD;
    const int blkN = (NN * 64 + 255) / 256;
    const int blkE = (EE * 64 + 255) / 256;

    // prologue: encoders + vn init
    k_encode_atoms<<<blkN, 256>>>(x, atom_emb, out);             // out slot 0 = h0
    k_encode_bonds<<<blkE, 256>>>(edge_attr, bond_emb);
    k_vn_init<<<(GG * DD + 255) / 256, 256>>>(vn_emb);

    for (int l = 0; l < LL; l++) {
        float* h = out + (size_t)l * slot;          // h_in storage == output slot l
        float* z_out = out + (size_t)(l + 1) * slot;

        // h_in = h_prev + vn[batch]   (in place -> this is also h_list[l])
        k_add_vn<<<blkN, 256>>>(h, batch);

        // edge message + scatter
        k_zero<<<(NN * 64 + 255) / 256, 256>>>(p_agg, NN * 64);
        k_edge_msg<<<blkE, 256>>>(edge_index, h);

        // z = (1+eps)h + agg
        k_gin_combine<<<blkN, 256>>>(h, gin_eps + l);

        // GIN MLP: Lin -> BN -> ReLU -> Lin
        dim3 gN((NN + BM - 1) / BM, DD / BNN);
        k_gemm_bias<<<gN, 256>>>(p_t, conv_W1 + (size_t)l * DD * DD,
                                 conv_b1 + l * DD, p_y, NN);
        bn_pipeline(p_y, p_y, conv_bn_g + l * DD, conv_bn_b + l * DD, NN, 1);
        k_gemm_bias<<<gN, 256>>>(p_y, conv_W2 + (size_t)l * DD * DD,
                                 conv_b2 + l * DD, p_t, NN);
        // outer BN (+relu except last) -> output slot l+1
        bn_pipeline(p_t, z_out, outer_bn_g + l * DD, outer_bn_b + l * DD, NN,
                    (l < LL - 1) ? 1 : 0);

        // virtual-node update
        if (l < LL - 1) {
            k_copy<<<(GG * 64 + 255) / 256, 256>>>(p_pooled, p_vn, GG * 64);
            k_pool_scatter<<<blkN, 256>>>(h, batch);
            dim3 gG((GG + BM - 1) / BM, DD / BNN);
            k_gemm_bias<<<gG, 256>>>(p_pooled, vn_W1 + (size_t)l * DD * DD,
                                     vn_b1 + l * DD, p_vt, GG);
            bn_pipeline(p_vt, p_vt, vn_bn1_g + l * DD, vn_bn1_b + l * DD, GG, 1);
            k_gemm_bias<<<gG, 256>>>(p_vt, vn_W2 + (size_t)l * DD * DD,
                                     vn_b2 + l * DD, p_vt2, GG);
            bn_pipeline(p_vt2, p_vn, vn_bn2_g + l * DD, vn_bn2_b + l * DD, GG, 1);
        }
    }
}

// round 2
// speedup vs baseline: 1.5388x; 1.5388x over previous
#include <cuda_runtime.h>
#include <cuda_bf16.h>
#include <cstdint>

#define NN 100000
#define EE 300000
#define GG 4096
#define DD 256
#define LL 5
#define BN_EPS 1e-5f

// ---------------- scratch (device globals; no allocations) ----------------
__device__ float g_ea[(size_t)EE * DD];      // bond embeddings per edge
__device__ float g_agg[(size_t)NN * DD];     // edge aggregation
__device__ float g_t[(size_t)NN * DD];       // gemm2 out
__device__ float g_y[(size_t)NN * DD];       // gemm1 out
__device__ float g_vn[(size_t)GG * DD];      // virtual node state
__device__ float g_pooled[(size_t)GG * DD];
__device__ float g_vt[(size_t)GG * DD];
__device__ float g_vt2[(size_t)GG * DD];
__device__ float g_stats[2 * DD];            // column sum / sumsq
__device__ float g_bnp[2 * DD];              // bn scale / shift

// ---------------- elementwise kernels ----------------
__global__ void k_zero(float* p, int n4) {
    int i = blockIdx.x * blockDim.x + threadIdx.x;
    if (i < n4) ((float4*)p)[i] = make_float4(0.f, 0.f, 0.f, 0.f);
}

__global__ void k_copy(float* dst, const float* src, int n4) {
    int i = blockIdx.x * blockDim.x + threadIdx.x;
    if (i < n4) ((float4*)dst)[i] = ((const float4*)src)[i];
}

__global__ void k_encode_atoms(const int* __restrict__ x,
                               const float* __restrict__ atom_emb,
                               float* __restrict__ out0) {
    int idx = blockIdx.x * blockDim.x + threadIdx.x;
    if (idx >= NN * 64) return;
    int n = idx >> 6;
    int d4 = (idx & 63) * 4;
    float4 acc = make_float4(0.f, 0.f, 0.f, 0.f);
#pragma unroll
    for (int f = 0; f < 9; f++) {
        int v = __ldg(&x[n * 9 + f]);
        float4 e = *(const float4*)(atom_emb + ((size_t)(f * 120 + v) * DD + d4));
        acc.x += e.x; acc.y += e.y; acc.z += e.z; acc.w += e.w;
    }
    *(float4*)(out0 + (size_t)n * DD + d4) = acc;
}

__global__ void k_encode_bonds(const int* __restrict__ ea_idx,
                               const float* __restrict__ bond_emb) {
    int idx = blockIdx.x * blockDim.x + threadIdx.x;
    if (idx >= EE * 64) return;
    int e = idx >> 6;
    int d4 = (idx & 63) * 4;
    float4 acc = make_float4(0.f, 0.f, 0.f, 0.f);
#pragma unroll
    for (int f = 0; f < 3; f++) {
        int v = __ldg(&ea_idx[e * 3 + f]);
        float4 em = *(const float4*)(bond_emb + ((size_t)(f * 6 + v) * DD + d4));
        acc.x += em.x; acc.y += em.y; acc.z += em.z; acc.w += em.w;
    }
    *(float4*)(g_ea + (size_t)e * DD + d4) = acc;
}

__global__ void k_vn_init(const float* __restrict__ vn_emb) {
    int i = blockIdx.x * blockDim.x + threadIdx.x;
    if (i < GG * DD) g_vn[i] = vn_emb[i & (DD - 1)];
}

__global__ void k_add_vn(float* __restrict__ h, const int* __restrict__ batch) {
    int idx = blockIdx.x * blockDim.x + threadIdx.x;
    if (idx >= NN * 64) return;
    int n = idx >> 6;
    int d4 = (idx & 63) * 4;
    int g = __ldg(&batch[n]);
    float4 v = *(float4*)(h + (size_t)n * DD + d4);
    float4 w = *(const float4*)(g_vn + (size_t)g * DD + d4);
    v.x += w.x; v.y += w.y; v.z += w.z; v.w += w.w;
    *(float4*)(h + (size_t)n * DD + d4) = v;
}

__global__ void k_edge_msg(const int* __restrict__ ei,
                           const float* __restrict__ h) {
    int idx = blockIdx.x * blockDim.x + threadIdx.x;
    if (idx >= EE * 64) return;
    int e = idx >> 6;
    int d4 = (idx & 63) * 4;
    int s = __ldg(&ei[e]);
    int t = __ldg(&ei[EE + e]);
    float4 hv = *(const float4*)(h + (size_t)s * DD + d4);
    float4 av = *(const float4*)(g_ea + (size_t)e * DD + d4);
    float m0 = fmaxf(hv.x + av.x, 0.f);
    float m1 = fmaxf(hv.y + av.y, 0.f);
    float m2 = fmaxf(hv.z + av.z, 0.f);
    float m3 = fmaxf(hv.w + av.w, 0.f);
    float* p = g_agg + (size_t)t * DD + d4;
    atomicAdd(p + 0, m0);
    atomicAdd(p + 1, m1);
    atomicAdd(p + 2, m2);
    atomicAdd(p + 3, m3);
}

__global__ void k_pool_scatter(const float* __restrict__ h,
                               const int* __restrict__ batch) {
    int idx = blockIdx.x * blockDim.x + threadIdx.x;
    if (idx >= NN * 64) return;
    int n = idx >> 6;
    int d4 = (idx & 63) * 4;
    int g = __ldg(&batch[n]);
    float4 v = *(const float4*)(h + (size_t)n * DD + d4);
    float* p = g_pooled + (size_t)g * DD + d4;
    atomicAdd(p + 0, v.x);
    atomicAdd(p + 1, v.y);
    atomicAdd(p + 2, v.z);
    atomicAdd(p + 3, v.w);
}

// ---------------- tensor-core GEMM: C[M,256] = op(A)[M,256] @ W[256,256] + bias
// 3-term bf16 split: a*b ~= a_hi*b_hi + a_hi*b_lo + a_lo*b_hi  (~5e-5 rel err)
// MODE 0: A as-is.  MODE 1: A = (1+eps)*h + agg.  MODE 2: A = relu(y*scale + shift) (BN fused)
#define BM 64
#define BK 32

__device__ __forceinline__ uint32_t pack_bf2(float a, float b) {
    __nv_bfloat162 t = __floats2bfloat162_rn(a, b);
    return *(uint32_t*)&t;
}

__device__ __forceinline__ void split_pack(float a, float b, uint32_t& hi, uint32_t& lo) {
    __nv_bfloat16 ah = __float2bfloat16_rn(a);
    __nv_bfloat16 bh = __float2bfloat16_rn(b);
    float al = a - __bfloat162float(ah);
    float bl = b - __bfloat162float(bh);
    __nv_bfloat162 h2; h2.x = ah; h2.y = bh;
    hi = *(uint32_t*)&h2;
    lo = pack_bf2(al, bl);
}

__device__ __forceinline__ void mma_bf16(float* c, const uint32_t* a, uint32_t b0, uint32_t b1) {
    asm volatile(
        "mma.sync.aligned.m16n8k16.row.col.f32.bf16.bf16.f32 "
        "{%0,%1,%2,%3}, {%4,%5,%6,%7}, {%8,%9}, {%0,%1,%2,%3};"
        : "+f"(c[0]), "+f"(c[1]), "+f"(c[2]), "+f"(c[3])
        : "r"(a[0]), "r"(a[1]), "r"(a[2]), "r"(a[3]), "r"(b0), "r"(b1));
}

template <int MODE>
__global__ void __launch_bounds__(256, 2)
k_gemm_mma(const float* __restrict__ A, const float* __restrict__ A2,
           const float* __restrict__ epsp, const float* __restrict__ W,
           const float* __restrict__ bias, float* __restrict__ C, int M) {
    __shared__ uint32_t As_hi[BK / 2][72];
    __shared__ uint32_t As_lo[BK / 2][72];
    __shared__ uint32_t Bs_hi[BK / 2][264];
    __shared__ uint32_t Bs_lo[BK / 2][264];

    int tid = threadIdx.x;
    int lane = tid & 31;
    int wid = tid >> 5;
    int wr = wid >> 2;        // 0..1
    int wc = wid & 3;         // 0..3
    int row0 = blockIdx.x * BM;

    float e = 0.f;
    if (MODE == 1) e = 1.0f + __ldg(epsp);

    float acc[2][8][4];
#pragma unroll
    for (int i = 0; i < 2; i++)
#pragma unroll
        for (int j = 0; j < 8; j++)
#pragma unroll
            for (int r = 0; r < 4; r++) acc[i][j][r] = 0.f;

    for (int k0 = 0; k0 < DD; k0 += BK) {
        // ---- A tile: 64 rows x 32 k (fp32 -> bf16 hi/lo split) ----
#pragma unroll
        for (int q = 0; q < 2; q++) {
            int li = tid + q * 256;        // 0..511
            int r = li >> 3;
            int kk = (li & 7) * 4;
            float4 v = make_float4(0.f, 0.f, 0.f, 0.f);
            int gr = row0 + r;
            if (gr < M) {
                size_t off = (size_t)gr * DD + k0 + kk;
                if (MODE == 0) {
                    v = *(const float4*)(A + off);
                } else if (MODE == 1) {
                    float4 hv = *(const float4*)(A + off);
                    float4 av = *(const float4*)(A2 + off);
                    v.x = e * hv.x + av.x; v.y = e * hv.y + av.y;
                    v.z = e * hv.z + av.z; v.w = e * hv.w + av.w;
                } else {
                    float4 yv = *(const float4*)(A + off);
                    float4 sc = *(const float4*)(g_bnp + k0 + kk);
                    float4 sh = *(const float4*)(g_bnp + DD + k0 + kk);
                    v.x = fmaxf(yv.x * sc.x + sh.x, 0.f);
                    v.y = fmaxf(yv.y * sc.y + sh.y, 0.f);
                    v.z = fmaxf(yv.z * sc.z + sh.z, 0.f);
                    v.w = fmaxf(yv.w * sc.w + sh.w, 0.f);
                }
            }
            int k2 = kk >> 1;
            uint32_t h0, l0, h1, l1;
            split_pack(v.x, v.y, h0, l0);
            split_pack(v.z, v.w, h1, l1);
            As_hi[k2][r] = h0;     As_lo[k2][r] = l0;
            As_hi[k2 + 1][r] = h1; As_lo[k2 + 1][r] = l1;
        }
        // ---- W tile: 32 k x 256 n ----
#pragma unroll
        for (int q = 0; q < 4; q++) {
            int li = tid + q * 256;        // 0..1023
            int k2 = li >> 6;
            int n4 = (li & 63) * 4;
            const float4 r0 = *(const float4*)(W + (size_t)(k0 + 2 * k2) * DD + n4);
            const float4 r1 = *(const float4*)(W + (size_t)(k0 + 2 * k2 + 1) * DD + n4);
            uint32_t h[4], l[4];
            split_pack(r0.x, r1.x, h[0], l[0]);
            split_pack(r0.y, r1.y, h[1], l[1]);
            split_pack(r0.z, r1.z, h[2], l[2]);
            split_pack(r0.w, r1.w, h[3], l[3]);
            *(uint4*)&Bs_hi[k2][n4] = *(uint4*)h;
            *(uint4*)&Bs_lo[k2][n4] = *(uint4*)l;
        }
        __syncthreads();

#pragma unroll
        for (int s = 0; s < 2; s++) {
            int kb = s * 8 + (lane & 3);
            uint32_t ah[2][4], al[2][4];
#pragma unroll
            for (int i = 0; i < 2; i++) {
                int m = wr * 32 + i * 16 + (lane >> 2);
                ah[i][0] = As_hi[kb][m];     ah[i][1] = As_hi[kb][m + 8];
                ah[i][2] = As_hi[kb + 4][m]; ah[i][3] = As_hi[kb + 4][m + 8];
                al[i][0] = As_lo[kb][m];     al[i][1] = As_lo[kb][m + 8];
                al[i][2] = As_lo[kb + 4][m]; al[i][3] = As_lo[kb + 4][m + 8];
            }
#pragma unroll
            for (int j = 0; j < 8; j++) {
                int n = wc * 64 + j * 8 + (lane >> 2);
                uint32_t bh0 = Bs_hi[kb][n], bh1 = Bs_hi[kb + 4][n];
                uint32_t bl0 = Bs_lo[kb][n], bl1 = Bs_lo[kb + 4][n];
#pragma unroll
                for (int i = 0; i < 2; i++) {
                    mma_bf16(acc[i][j], ah[i], bh0, bh1);
                    mma_bf16(acc[i][j], ah[i], bl0, bl1);
                    mma_bf16(acc[i][j], al[i], bh0, bh1);
                }
            }
        }
        __syncthreads();
    }

    // ---- epilogue: += bias, store fp32 ----
#pragma unroll
    for (int i = 0; i < 2; i++) {
        int gr = row0 + wr * 32 + i * 16 + (lane >> 2);
#pragma unroll
        for (int j = 0; j < 8; j++) {
            int gc = wc * 64 + j * 8 + (lane & 3) * 2;
            float bx = __ldg(&bias[gc]);
            float by = __ldg(&bias[gc + 1]);
            if (gr < M) {
                float2 v0 = make_float2(acc[i][j][0] + bx, acc[i][j][1] + by);
                *(float2*)(C + (size_t)gr * DD + gc) = v0;
            }
            if (gr + 8 < M) {
                float2 v1 = make_float2(acc[i][j][2] + bx, acc[i][j][3] + by);
                *(float2*)(C + (size_t)(gr + 8) * DD + gc) = v1;
            }
        }
    }
}

// ---------------- BatchNorm (training-mode, batch stats) ----------------
__global__ void k_zero_stats() {
    int i = threadIdx.x;
    if (i < 2 * DD) g_stats[i] = 0.f;
}

__global__ void k_colstats(const float* __restrict__ Y, int M) {
    int col = threadIdx.x;
    int rows_per = (M + gridDim.x - 1) / gridDim.x;
    int r0 = blockIdx.x * rows_per;
    int r1 = min(M, r0 + rows_per);
    float s = 0.f, s2 = 0.f;
    for (int r = r0; r < r1; r++) {
        float v = Y[(size_t)r * DD + col];
        s += v;
        s2 += v * v;
    }
    atomicAdd(&g_stats[col], s);
    atomicAdd(&g_stats[DD + col], s2);
}

__global__ void k_bn_prep(const float* __restrict__ gamma, const float* __restrict__ beta,
                          float Minv) {
    int c = threadIdx.x;  // 256
    float m = g_stats[c] * Minv;
    float var = g_stats[DD + c] * Minv - m * m;
    float rs = rsqrtf(var + BN_EPS);
    float sc = gamma[c] * rs;
    g_bnp[c] = sc;
    g_bnp[DD + c] = beta[c] - m * sc;
}

__global__ void k_bn_apply(const float* __restrict__ Yin, float* __restrict__ Yout,
                           const float* __restrict__ gamma, const float* __restrict__ beta,
                           int M, int do_relu) {
    int idx = blockIdx.x * blockDim.x + threadIdx.x;
    if (idx >= M * 64) return;
    int r = idx >> 6;
    int c4 = (idx & 63) * 4;
    float inv = 1.0f / (float)M;
    float4 s = *(const float4*)(g_stats + c4);
    float4 s2 = *(const float4*)(g_stats + DD + c4);
    float4 g = *(const float4*)(gamma + c4);
    float4 b = *(const float4*)(beta + c4);
    float4 v = *(const float4*)(Yin + (size_t)r * DD + c4);
    float m, var, rs, o;
#define BN1(X)                                             \
    m = s.X * inv;                                         \
    var = s2.X * inv - m * m;                              \
    rs = rsqrtf(var + BN_EPS);                             \
    o = (v.X - m) * rs * g.X + b.X;                        \
    if (do_relu) o = fmaxf(o, 0.f);                        \
    v.X = o;
    BN1(x) BN1(y) BN1(z) BN1(w)
#undef BN1
    *(float4*)(Yout + (size_t)r * DD + c4) = v;
}

// ---------------- host orchestration ----------------
static inline void run_colstats(const float* Y, int M) {
    k_zero_stats<<<1, 512>>>();
    int nblk = (M >= 32768) ? 512 : 64;
    k_colstats<<<nblk, 256>>>(Y, M);
}

extern "C" void kernel_launch(void* const* d_in, const int* in_sizes, int n_in,
                              void* d_out, int out_size) {
    const int* x          = (const int*)d_in[0];
    const int* edge_index = (const int*)d_in[1];
    const int* edge_attr  = (const int*)d_in[2];
    const int* batch      = (const int*)d_in[3];
    const float* atom_emb = (const float*)d_in[4];
    const float* bond_emb = (const float*)d_in[5];
    const float* vn_emb   = (const float*)d_in[6];
    const float* gin_eps  = (const float*)d_in[7];
    const float* conv_W1  = (const float*)d_in[8];
    const float* conv_b1  = (const float*)d_in[9];
    const float* conv_bn_g = (const float*)d_in[10];
    const float* conv_bn_b = (const float*)d_in[11];
    const float* conv_W2  = (const float*)d_in[12];
    const float* conv_b2  = (const float*)d_in[13];
    const float* outer_bn_g = (const float*)d_in[14];
    const float* outer_bn_b = (const float*)d_in[15];
    const float* vn_W1    = (const float*)d_in[16];
    const float* vn_b1    = (const float*)d_in[17];
    const float* vn_bn1_g = (const float*)d_in[18];
    const float* vn_bn1_b = (const float*)d_in[19];
    const float* vn_W2    = (const float*)d_in[20];
    const float* vn_b2    = (const float*)d_in[21];
    const float* vn_bn2_g = (const float*)d_in[22];
    const float* vn_bn2_b = (const float*)d_in[23];
    float* out = (float*)d_out;

    float *p_agg, *p_t, *p_y, *p_pooled, *p_vt, *p_vt2, *p_vn;
    cudaGetSymbolAddress((void**)&p_agg, g_agg);
    cudaGetSymbolAddress((void**)&p_t, g_t);
    cudaGetSymbolAddress((void**)&p_y, g_y);
    cudaGetSymbolAddress((void**)&p_pooled, g_pooled);
    cudaGetSymbolAddress((void**)&p_vt, g_vt);
    cudaGetSymbolAddress((void**)&p_vt2, g_vt2);
    cudaGetSymbolAddress((void**)&p_vn, g_vn);

    const size_t slot = (size_t)NN * DD;
    const int blkN = (NN * 64 + 255) / 256;
    const int blkE = (EE * 64 + 255) / 256;
    const float invN = 1.0f / (float)NN;
    const float invG = 1.0f / (float)GG;

    k_encode_atoms<<<blkN, 256>>>(x, atom_emb, out);   // out slot 0 = h0
    k_encode_bonds<<<blkE, 256>>>(edge_attr, bond_emb);
    k_vn_init<<<(GG * DD + 255) / 256, 256>>>(vn_emb);

    const int gBigM = (NN + BM - 1) / BM;
    const int gSmallM = (GG + BM - 1) / BM;

    for (int l = 0; l < LL; l++) {
        float* h = out + (size_t)l * slot;
        float* z_out = out + (size_t)(l + 1) * slot;

        // h_in = h_prev + vn[batch] (in place; this is h_list[l])
        k_add_vn<<<blkN, 256>>>(h, batch);

        // edge message + scatter
        k_zero<<<(NN * 64 + 255) / 256, 256>>>(p_agg, NN * 64);
        k_edge_msg<<<blkE, 256>>>(edge_index, h);

        // GEMM1 with fused gin_combine: ((1+eps)h + agg) @ W1 + b1
        k_gemm_mma<1><<<gBigM, 256>>>(h, p_agg, gin_eps + l,
                                      conv_W1 + (size_t)l * DD * DD,
                                      conv_b1 + l * DD, p_y, NN);
        // BN stats + prep, then GEMM2 with fused BN+ReLU on input
        run_colstats(p_y, NN);
        k_bn_prep<<<1, 256>>>(conv_bn_g + l * DD, conv_bn_b + l * DD, invN);
        k_gemm_mma<2><<<gBigM, 256>>>(p_y, nullptr, nullptr,
                                      conv_W2 + (size_t)l * DD * DD,
                                      conv_b2 + l * DD, p_t, NN);
        // outer BN (+relu except last) -> output slot l+1
        run_colstats(p_t, NN);
        k_bn_apply<<<blkN, 256>>>(p_t, z_out, outer_bn_g + l * DD,
                                  outer_bn_b + l * DD, NN, (l < LL - 1) ? 1 : 0);

        // virtual-node update
        if (l < LL - 1) {
            k_copy<<<(GG * 64 + 255) / 256, 256>>>(p_pooled, p_vn, GG * 64);
            k_pool_scatter<<<blkN, 256>>>(h, batch);
            k_gemm_mma<0><<<gSmallM, 256>>>(p_pooled, nullptr, nullptr,
                                            vn_W1 + (size_t)l * DD * DD,
                                            vn_b1 + l * DD, p_vt, GG);
            run_colstats(p_vt, GG);
            k_bn_prep<<<1, 256>>>(vn_bn1_g + l * DD, vn_bn1_b + l * DD, invG);
            k_gemm_mma<2><<<gSmallM, 256>>>(p_vt, nullptr, nullptr,
                                            vn_W2 + (size_t)l * DD * DD,
                                            vn_b2 + l * DD, p_vt2, GG);
            run_colstats(p_vt2, GG);
            k_bn_apply<<<(GG * 64 + 255) / 256, 256>>>(p_vt2, p_vn, vn_bn2_g + l * DD,
                                                       vn_bn2_b + l * DD, GG, 1);
        }
    }
}

// round 3
// speedup vs baseline: 2.1230x; 1.3797x over previous
#include <cuda_runtime.h>
#include <cuda_bf16.h>
#include <cstdint>

#define NN 100000
#define EE 300000
#define GG 4096
#define DD 256
#define LL 5
#define BN_EPS 1e-5f

// ---------------- scratch (device globals; no allocations) ----------------
__device__ __nv_bfloat162 g_ea[(size_t)EE * 128];  // bond embeddings per edge (bf16)
__device__ float g_agg[(size_t)NN * DD];           // edge aggregation
__device__ float g_t[(size_t)NN * DD];             // gemm2 out
__device__ float g_y[(size_t)NN * DD];             // gemm1 out
__device__ float g_vn[(size_t)GG * DD];            // virtual node state
__device__ float g_pooled[(size_t)GG * DD];
__device__ float g_vt[(size_t)GG * DD];
__device__ float g_vt2[(size_t)GG * DD];
__device__ float g_stats[2 * DD];                  // column sum / sumsq
__device__ float g_bnp[2 * DD];                    // bn scale / shift

__device__ __forceinline__ void red2(float* p, float a, float b) {
    asm volatile("red.global.add.v2.f32 [%0], {%1,%2};" :: "l"(p), "f"(a), "f"(b) : "memory");
}
__device__ __forceinline__ void red4(float* p, float a, float b, float c, float d) {
    asm volatile("red.global.add.v4.f32 [%0], {%1,%2,%3,%4};"
                 :: "l"(p), "f"(a), "f"(b), "f"(c), "f"(d) : "memory");
}

// ---------------- elementwise kernels ----------------
__global__ void k_zero(float* p, int n4) {
    int i = blockIdx.x * blockDim.x + threadIdx.x;
    if (i < n4) ((float4*)p)[i] = make_float4(0.f, 0.f, 0.f, 0.f);
}

__global__ void k_copy(float* dst, const float* src, int n4) {
    int i = blockIdx.x * blockDim.x + threadIdx.x;
    if (i < n4) ((float4*)dst)[i] = ((const float4*)src)[i];
}

__global__ void k_zero_stats() {
    int i = threadIdx.x;
    if (i < 2 * DD) g_stats[i] = 0.f;
}

// atom encoder with fused + vn_emb broadcast (h_in^0 = sum emb + vn0)
__global__ void k_encode_atoms(const int* __restrict__ x,
                               const float* __restrict__ atom_emb,
                               const float* __restrict__ vn_emb,
                               float* __restrict__ out0) {
    int idx = blockIdx.x * blockDim.x + threadIdx.x;
    if (idx >= NN * 64) return;
    int n = idx >> 6;
    int d4 = (idx & 63) * 4;
    float4 acc = *(const float4*)(vn_emb + d4);
#pragma unroll
    for (int f = 0; f < 9; f++) {
        int v = __ldg(&x[n * 9 + f]);
        float4 e = *(const float4*)(atom_emb + ((size_t)(f * 120 + v) * DD + d4));
        acc.x += e.x; acc.y += e.y; acc.z += e.z; acc.w += e.w;
    }
    *(float4*)(out0 + (size_t)n * DD + d4) = acc;
}

__global__ void k_encode_bonds(const int* __restrict__ ea_idx,
                               const float* __restrict__ bond_emb) {
    int idx = blockIdx.x * blockDim.x + threadIdx.x;
    if (idx >= EE * 64) return;
    int e = idx >> 6;
    int d4 = (idx & 63) * 4;
    float4 acc = make_float4(0.f, 0.f, 0.f, 0.f);
#pragma unroll
    for (int f = 0; f < 3; f++) {
        int v = __ldg(&ea_idx[e * 3 + f]);
        float4 em = *(const float4*)(bond_emb + ((size_t)(f * 6 + v) * DD + d4));
        acc.x += em.x; acc.y += em.y; acc.z += em.z; acc.w += em.w;
    }
    __nv_bfloat162 b0 = __floats2bfloat162_rn(acc.x, acc.y);
    __nv_bfloat162 b1 = __floats2bfloat162_rn(acc.z, acc.w);
    g_ea[(size_t)e * 128 + (d4 >> 1)] = b0;
    g_ea[(size_t)e * 128 + (d4 >> 1) + 1] = b1;
}

__global__ void k_vn_init(const float* __restrict__ vn_emb) {
    int i = blockIdx.x * blockDim.x + threadIdx.x;
    if (i < GG * DD) g_vn[i] = vn_emb[i & (DD - 1)];
}

__global__ void k_edge_msg(const int* __restrict__ ei,
                           const float* __restrict__ h) {
    int idx = blockIdx.x * blockDim.x + threadIdx.x;
    if (idx >= EE * 64) return;
    int e = idx >> 6;
    int d4 = (idx & 63) * 4;
    int s = __ldg(&ei[e]);
    int t = __ldg(&ei[EE + e]);
    float4 hv = *(const float4*)(h + (size_t)s * DD + d4);
    __nv_bfloat162 a0 = g_ea[(size_t)e * 128 + (d4 >> 1)];
    __nv_bfloat162 a1 = g_ea[(size_t)e * 128 + (d4 >> 1) + 1];
    float m0 = fmaxf(hv.x + __bfloat162float(a0.x), 0.f);
    float m1 = fmaxf(hv.y + __bfloat162float(a0.y), 0.f);
    float m2 = fmaxf(hv.z + __bfloat162float(a1.x), 0.f);
    float m3 = fmaxf(hv.w + __bfloat162float(a1.y), 0.f);
    red4(g_agg + (size_t)t * DD + d4, m0, m1, m2, m3);
}

__global__ void k_pool_scatter(const float* __restrict__ h,
                               const int* __restrict__ batch) {
    int idx = blockIdx.x * blockDim.x + threadIdx.x;
    if (idx >= NN * 64) return;
    int n = idx >> 6;
    int d4 = (idx & 63) * 4;
    int g = __ldg(&batch[n]);
    float4 v = *(const float4*)(h + (size_t)n * DD + d4);
    red4(g_pooled + (size_t)g * DD + d4, v.x, v.y, v.z, v.w);
}

// ---------------- tensor-core GEMM: C[M,256] = op(A)[M,256] @ W[256,256] + bias
// 3-term bf16 split. Epilogue also accumulates per-column sum/sumsq into g_stats.
// MODE 0: A as-is. MODE 1: A=(1+eps)h+agg. MODE 2: A=relu(y*scale+shift) (BN fused)
#define BM 64
#define BK 32

__device__ __forceinline__ uint32_t pack_bf2(float a, float b) {
    __nv_bfloat162 t = __floats2bfloat162_rn(a, b);
    return *(uint32_t*)&t;
}

__device__ __forceinline__ void split_pack(float a, float b, uint32_t& hi, uint32_t& lo) {
    __nv_bfloat16 ah = __float2bfloat16_rn(a);
    __nv_bfloat16 bh = __float2bfloat16_rn(b);
    float al = a - __bfloat162float(ah);
    float bl = b - __bfloat162float(bh);
    __nv_bfloat162 h2; h2.x = ah; h2.y = bh;
    hi = *(uint32_t*)&h2;
    lo = pack_bf2(al, bl);
}

__device__ __forceinline__ void mma_bf16(float* c, const uint32_t* a, uint32_t b0, uint32_t b1) {
    asm volatile(
        "mma.sync.aligned.m16n8k16.row.col.f32.bf16.bf16.f32 "
        "{%0,%1,%2,%3}, {%4,%5,%6,%7}, {%8,%9}, {%0,%1,%2,%3};"
        : "+f"(c[0]), "+f"(c[1]), "+f"(c[2]), "+f"(c[3])
        : "r"(a[0]), "r"(a[1]), "r"(a[2]), "r"(a[3]), "r"(b0), "r"(b1));
}

template <int MODE>
__global__ void __launch_bounds__(256, 2)
k_gemm_mma(const float* __restrict__ A, const float* __restrict__ A2,
           const float* __restrict__ epsp, const float* __restrict__ W,
           const float* __restrict__ bias, float* __restrict__ C, int M) {
    __shared__ uint32_t As_hi[BK / 2][72];
    __shared__ uint32_t As_lo[BK / 2][72];
    __shared__ uint32_t Bs_hi[BK / 2][264];
    __shared__ uint32_t Bs_lo[BK / 2][264];

    int tid = threadIdx.x;
    int lane = tid & 31;
    int wid = tid >> 5;
    int wr = wid >> 2;        // 0..1
    int wc = wid & 3;         // 0..3
    int row0 = blockIdx.x * BM;

    float e = 0.f;
    if (MODE == 1) e = 1.0f + __ldg(epsp);

    float acc[2][8][4];
#pragma unroll
    for (int i = 0; i < 2; i++)
#pragma unroll
        for (int j = 0; j < 8; j++)
#pragma unroll
            for (int r = 0; r < 4; r++) acc[i][j][r] = 0.f;

    for (int k0 = 0; k0 < DD; k0 += BK) {
        // ---- A tile: 64 rows x 32 k (fp32 -> bf16 hi/lo split) ----
#pragma unroll
        for (int q = 0; q < 2; q++) {
            int li = tid + q * 256;
            int r = li >> 3;
            int kk = (li & 7) * 4;
            float4 v = make_float4(0.f, 0.f, 0.f, 0.f);
            int gr = row0 + r;
            if (gr < M) {
                size_t off = (size_t)gr * DD + k0 + kk;
                if (MODE == 0) {
                    v = *(const float4*)(A + off);
                } else if (MODE == 1) {
                    float4 hv = *(const float4*)(A + off);
                    float4 av = *(const float4*)(A2 + off);
                    v.x = e * hv.x + av.x; v.y = e * hv.y + av.y;
                    v.z = e * hv.z + av.z; v.w = e * hv.w + av.w;
                } else {
                    float4 yv = *(const float4*)(A + off);
                    float4 sc = *(const float4*)(g_bnp + k0 + kk);
                    float4 sh = *(const float4*)(g_bnp + DD + k0 + kk);
                    v.x = fmaxf(yv.x * sc.x + sh.x, 0.f);
                    v.y = fmaxf(yv.y * sc.y + sh.y, 0.f);
                    v.z = fmaxf(yv.z * sc.z + sh.z, 0.f);
                    v.w = fmaxf(yv.w * sc.w + sh.w, 0.f);
                }
            }
            int k2 = kk >> 1;
            uint32_t h0, l0, h1, l1;
            split_pack(v.x, v.y, h0, l0);
            split_pack(v.z, v.w, h1, l1);
            As_hi[k2][r] = h0;     As_lo[k2][r] = l0;
            As_hi[k2 + 1][r] = h1; As_lo[k2 + 1][r] = l1;
        }
        // ---- W tile: 32 k x 256 n ----
#pragma unroll
        for (int q = 0; q < 4; q++) {
            int li = tid + q * 256;
            int k2 = li >> 6;
            int n4 = (li & 63) * 4;
            const float4 r0 = *(const float4*)(W + (size_t)(k0 + 2 * k2) * DD + n4);
            const float4 r1 = *(const float4*)(W + (size_t)(k0 + 2 * k2 + 1) * DD + n4);
            uint32_t h[4], l[4];
            split_pack(r0.x, r1.x, h[0], l[0]);
            split_pack(r0.y, r1.y, h[1], l[1]);
            split_pack(r0.z, r1.z, h[2], l[2]);
            split_pack(r0.w, r1.w, h[3], l[3]);
            *(uint4*)&Bs_hi[k2][n4] = *(uint4*)h;
            *(uint4*)&Bs_lo[k2][n4] = *(uint4*)l;
        }
        __syncthreads();

#pragma unroll
        for (int s = 0; s < 2; s++) {
            int kb = s * 8 + (lane & 3);
            uint32_t ah[2][4], al[2][4];
#pragma unroll
            for (int i = 0; i < 2; i++) {
                int m = wr * 32 + i * 16 + (lane >> 2);
                ah[i][0] = As_hi[kb][m];     ah[i][1] = As_hi[kb][m + 8];
                ah[i][2] = As_hi[kb + 4][m]; ah[i][3] = As_hi[kb + 4][m + 8];
                al[i][0] = As_lo[kb][m];     al[i][1] = As_lo[kb][m + 8];
                al[i][2] = As_lo[kb + 4][m]; al[i][3] = As_lo[kb + 4][m + 8];
            }
#pragma unroll
            for (int j = 0; j < 8; j++) {
                int n = wc * 64 + j * 8 + (lane >> 2);
                uint32_t bh0 = Bs_hi[kb][n], bh1 = Bs_hi[kb + 4][n];
                uint32_t bl0 = Bs_lo[kb][n], bl1 = Bs_lo[kb + 4][n];
#pragma unroll
                for (int i = 0; i < 2; i++) {
                    mma_bf16(acc[i][j], ah[i], bh0, bh1);
                    mma_bf16(acc[i][j], ah[i], bl0, bl1);
                    mma_bf16(acc[i][j], al[i], bh0, bh1);
                }
            }
        }
        __syncthreads();
    }

    // ---- epilogue: += bias, store fp32, fused per-column sum/sumsq ----
#pragma unroll
    for (int j = 0; j < 8; j++) {
        int gc = wc * 64 + j * 8 + (lane & 3) * 2;
        float bx = __ldg(&bias[gc]);
        float by = __ldg(&bias[gc + 1]);
        float sx = 0.f, sy = 0.f, qx = 0.f, qy = 0.f;
#pragma unroll
        for (int i = 0; i < 2; i++) {
            int gr = row0 + wr * 32 + i * 16 + (lane >> 2);
            if (gr < M) {
                float2 v0 = make_float2(acc[i][j][0] + bx, acc[i][j][1] + by);
                *(float2*)(C + (size_t)gr * DD + gc) = v0;
                sx += v0.x; sy += v0.y; qx += v0.x * v0.x; qy += v0.y * v0.y;
            }
            if (gr + 8 < M) {
                float2 v1 = make_float2(acc[i][j][2] + bx, acc[i][j][3] + by);
                *(float2*)(C + (size_t)(gr + 8) * DD + gc) = v1;
                sx += v1.x; sy += v1.y; qx += v1.x * v1.x; qy += v1.y * v1.y;
            }
        }
        // reduce over the 8 row-lanes (lane bits 2..4)
#pragma unroll
        for (int d = 4; d < 32; d <<= 1) {
            sx += __shfl_xor_sync(0xffffffff, sx, d);
            sy += __shfl_xor_sync(0xffffffff, sy, d);
            qx += __shfl_xor_sync(0xffffffff, qx, d);
            qy += __shfl_xor_sync(0xffffffff, qy, d);
        }
        if ((lane >> 2) == 0) {
            red2(&g_stats[gc], sx, sy);
            red2(&g_stats[DD + gc], qx, qy);
        }
    }
}

// ---------------- BN prep: stats -> scale/shift, then zero stats ----------------
__global__ void k_bn_prep(const float* __restrict__ gamma, const float* __restrict__ beta,
                          float Minv) {
    int c = threadIdx.x;  // 256
    float m = g_stats[c] * Minv;
    float var = g_stats[DD + c] * Minv - m * m;
    float rs = rsqrtf(var + BN_EPS);
    float sc = gamma[c] * rs;
    g_bnp[c] = sc;
    g_bnp[DD + c] = beta[c] - m * sc;
    g_stats[c] = 0.f;
    g_stats[DD + c] = 0.f;
}

// BN apply using g_bnp (+ optional relu, + optional fused vn[batch] gather)
__global__ void k_bn_apply(const float* __restrict__ Yin, float* __restrict__ Yout,
                           const int* __restrict__ batch, int M, int do_relu, int do_vn) {
    int idx = blockIdx.x * blockDim.x + threadIdx.x;
    if (idx >= M * 64) return;
    int r = idx >> 6;
    int c4 = (idx & 63) * 4;
    float4 sc = *(const float4*)(g_bnp + c4);
    float4 sh = *(const float4*)(g_bnp + DD + c4);
    float4 v = *(const float4*)(Yin + (size_t)r * DD + c4);
    v.x = v.x * sc.x + sh.x;
    v.y = v.y * sc.y + sh.y;
    v.z = v.z * sc.z + sh.z;
    v.w = v.w * sc.w + sh.w;
    if (do_relu) {
        v.x = fmaxf(v.x, 0.f); v.y = fmaxf(v.y, 0.f);
        v.z = fmaxf(v.z, 0.f); v.w = fmaxf(v.w, 0.f);
    }
    if (do_vn) {
        int g = __ldg(&batch[r]);
        float4 w = *(const float4*)(g_vn + (size_t)g * DD + c4);
        v.x += w.x; v.y += w.y; v.z += w.z; v.w += w.w;
    }
    *(float4*)(Yout + (size_t)r * DD + c4) = v;
}

// ---------------- host orchestration ----------------
extern "C" void kernel_launch(void* const* d_in, const int* in_sizes, int n_in,
                              void* d_out, int out_size) {
    const int* x          = (const int*)d_in[0];
    const int* edge_index = (const int*)d_in[1];
    const int* edge_attr  = (const int*)d_in[2];
    const int* batch      = (const int*)d_in[3];
    const float* atom_emb = (const float*)d_in[4];
    const float* bond_emb = (const float*)d_in[5];
    const float* vn_emb   = (const float*)d_in[6];
    const float* gin_eps  = (const float*)d_in[7];
    const float* conv_W1  = (const float*)d_in[8];
    const float* conv_b1  = (const float*)d_in[9];
    const float* conv_bn_g = (const float*)d_in[10];
    const float* conv_bn_b = (const float*)d_in[11];
    const float* conv_W2  = (const float*)d_in[12];
    const float* conv_b2  = (const float*)d_in[13];
    const float* outer_bn_g = (const float*)d_in[14];
    const float* outer_bn_b = (const float*)d_in[15];
    const float* vn_W1    = (const float*)d_in[16];
    const float* vn_b1    = (const float*)d_in[17];
    const float* vn_bn1_g = (const float*)d_in[18];
    const float* vn_bn1_b = (const float*)d_in[19];
    const float* vn_W2    = (const float*)d_in[20];
    const float* vn_b2    = (const float*)d_in[21];
    const float* vn_bn2_g = (const float*)d_in[22];
    const float* vn_bn2_b = (const float*)d_in[23];
    float* out = (float*)d_out;

    float *p_agg, *p_t, *p_y, *p_pooled, *p_vt, *p_vt2, *p_vn;
    cudaGetSymbolAddress((void**)&p_agg, g_agg);
    cudaGetSymbolAddress((void**)&p_t, g_t);
    cudaGetSymbolAddress((void**)&p_y, g_y);
    cudaGetSymbolAddress((void**)&p_pooled, g_pooled);
    cudaGetSymbolAddress((void**)&p_vt, g_vt);
    cudaGetSymbolAddress((void**)&p_vt2, g_vt2);
    cudaGetSymbolAddress((void**)&p_vn, g_vn);

    const size_t slot = (size_t)NN * DD;
    const int blkN = (NN * 64 + 255) / 256;
    const int blkE = (EE * 64 + 255) / 256;
    const float invN = 1.0f / (float)NN;
    const float invG = 1.0f / (float)GG;

    // prologue
    k_encode_atoms<<<blkN, 256>>>(x, atom_emb, vn_emb, out);  // slot 0 = h0 + vn0
    k_encode_bonds<<<blkE, 256>>>(edge_attr, bond_emb);
    k_vn_init<<<(GG * DD + 255) / 256, 256>>>(vn_emb);
    k_zero_stats<<<1, 512>>>();

    const int gBigM = (NN + BM - 1) / BM;
    const int gSmallM = (GG + BM - 1) / BM;

    for (int l = 0; l < LL; l++) {
        float* h = out + (size_t)l * slot;            // h_in^l (vn already added)
        float* z_out = out + (size_t)(l + 1) * slot;

        // edge message + scatter
        k_zero<<<(NN * 64 + 255) / 256, 256>>>(p_agg, NN * 64);
        k_edge_msg<<<blkE, 256>>>(edge_index, h);

        // virtual-node update FIRST (only needs h); result consumed by bn_apply below
        if (l < LL - 1) {
            k_copy<<<(GG * 64 + 255) / 256, 256>>>(p_pooled, p_vn, GG * 64);
            k_pool_scatter<<<blkN, 256>>>(h, batch);
            k_gemm_mma<0><<<gSmallM, 256>>>(p_pooled, nullptr, nullptr,
                                            vn_W1 + (size_t)l * DD * DD,
                                            vn_b1 + l * DD, p_vt, GG);
            k_bn_prep<<<1, 256>>>(vn_bn1_g + l * DD, vn_bn1_b + l * DD, invG);
            k_gemm_mma<2><<<gSmallM, 256>>>(p_vt, nullptr, nullptr,
                                            vn_W2 + (size_t)l * DD * DD,
                                            vn_b2 + l * DD, p_vt2, GG);
            k_bn_prep<<<1, 256>>>(vn_bn2_g + l * DD, vn_bn2_b + l * DD, invG);
            k_bn_apply<<<(GG * 64 + 255) / 256, 256>>>(p_vt2, p_vn, nullptr, GG, 1, 0);
        }

        // GEMM1 fused gin_combine + stats
        k_gemm_mma<1><<<gBigM, 256>>>(h, p_agg, gin_eps + l,
                                      conv_W1 + (size_t)l * DD * DD,
                                      conv_b1 + l * DD, p_y, NN);
        k_bn_prep<<<1, 256>>>(conv_bn_g + l * DD, conv_bn_b + l * DD, invN);
        // GEMM2 fused BN+ReLU on input + stats
        k_gemm_mma<2><<<gBigM, 256>>>(p_y, nullptr, nullptr,
                                      conv_W2 + (size_t)l * DD * DD,
                                      conv_b2 + l * DD, p_t, NN);
        k_bn_prep<<<1, 256>>>(outer_bn_g + l * DD, outer_bn_b + l * DD, invN);
        // outer BN apply (+relu, +vn_new[batch]) -> slot l+1 = h_in^{l+1}
        k_bn_apply<<<blkN, 256>>>(p_t, z_out, batch, NN,
                                  (l < LL - 1) ? 1 : 0, (l < LL - 1) ? 1 : 0);
    }
}

// round 4
// speedup vs baseline: 2.4089x; 1.1347x over previous
#include <cuda_runtime.h>
#include <cuda_bf16.h>
#include <cstdint>

#define NN 100000
#define EE 300000
#define GG 4096
#define DD 256
#define LL 5
#define BN_EPS 1e-5f
#define NW 18   // weight matrices: conv_W1[5], conv_W2[5], vn_W1[4], vn_W2[4]

// ---------------- scratch (device globals; no allocations) ----------------
__device__ uint16_t g_ecode[EE];                   // bond code per edge (216 values)
__device__ float g_lut[216 * DD];                  // bond-embedding LUT (fp32)
__device__ float g_agg[(size_t)NN * DD];           // edge aggregation
__device__ float g_t[(size_t)NN * DD];             // gemm2 out
__device__ float g_y[(size_t)NN * DD];             // gemm1 out
__device__ float g_vn[(size_t)GG * DD];            // virtual node state
__device__ float g_pooled[(size_t)GG * DD];        // raw pooled sum (no vn)
__device__ float g_vt[(size_t)GG * DD];
__device__ float g_vt2[(size_t)GG * DD];
__device__ float g_stats[2 * DD];                  // column sum / sumsq
__device__ float g_bnp[2 * DD];                    // bn scale / shift
__device__ uint32_t g_whi[(size_t)NW * 128 * DD];  // pre-split W (bf16 hi, k-pairs packed)
__device__ uint32_t g_wlo[(size_t)NW * 128 * DD];  // pre-split W (bf16 lo)

__device__ __forceinline__ void red2(float* p, float a, float b) {
    asm volatile("red.global.add.v2.f32 [%0], {%1,%2};" :: "l"(p), "f"(a), "f"(b) : "memory");
}
__device__ __forceinline__ void red4(float* p, float a, float b, float c, float d) {
    asm volatile("red.global.add.v4.f32 [%0], {%1,%2,%3,%4};"
                 :: "l"(p), "f"(a), "f"(b), "f"(c), "f"(d) : "memory");
}

__device__ __forceinline__ uint32_t pack_bf2(float a, float b) {
    __nv_bfloat162 t = __floats2bfloat162_rn(a, b);
    return *(uint32_t*)&t;
}
__device__ __forceinline__ void split_pack(float a, float b, uint32_t& hi, uint32_t& lo) {
    __nv_bfloat16 ah = __float2bfloat16_rn(a);
    __nv_bfloat16 bh = __float2bfloat16_rn(b);
    float al = a - __bfloat162float(ah);
    float bl = b - __bfloat162float(bh);
    __nv_bfloat162 h2; h2.x = ah; h2.y = bh;
    hi = *(uint32_t*)&h2;
    lo = pack_bf2(al, bl);
}

// ---------------- small kernels ----------------
__global__ void k_zero(float* p, int n4) {
    int i = blockIdx.x * blockDim.x + threadIdx.x;
    if (i < n4) ((float4*)p)[i] = make_float4(0.f, 0.f, 0.f, 0.f);
}

__global__ void k_zero_stats() {
    int i = threadIdx.x;
    if (i < 2 * DD) g_stats[i] = 0.f;
}

// pre-split one 256x256 weight matrix into packed bf16 hi/lo (k-pairs along rows)
__global__ void k_split_w(const float* __restrict__ W, uint32_t* __restrict__ hi,
                          uint32_t* __restrict__ lo) {
    int i = blockIdx.x * blockDim.x + threadIdx.x;  // over 128*256
    if (i >= 128 * DD) return;
    int k2 = i >> 8, n = i & 255;
    float a = W[(size_t)(2 * k2) * DD + n];
    float b = W[(size_t)(2 * k2 + 1) * DD + n];
    split_pack(a, b, hi[i], lo[i]);
}

__global__ void k_edge_code(const int* __restrict__ ea_idx) {
    int e = blockIdx.x * blockDim.x + threadIdx.x;
    if (e >= EE) return;
    int v0 = ea_idx[e * 3 + 0], v1 = ea_idx[e * 3 + 1], v2 = ea_idx[e * 3 + 2];
    g_ecode[e] = (uint16_t)(v0 * 36 + v1 * 6 + v2);
}

__global__ void k_build_lut(const float* __restrict__ bond_emb) {
    int idx = blockIdx.x * blockDim.x + threadIdx.x;  // over 216*64
    if (idx >= 216 * 64) return;
    int c = idx >> 6;
    int d4 = (idx & 63) * 4;
    int v0 = c / 36, v1 = (c / 6) % 6, v2 = c % 6;
    float4 a = *(const float4*)(bond_emb + ((size_t)(0 * 6 + v0) * DD + d4));
    float4 b = *(const float4*)(bond_emb + ((size_t)(1 * 6 + v1) * DD + d4));
    float4 d = *(const float4*)(bond_emb + ((size_t)(2 * 6 + v2) * DD + d4));
    float4 o = make_float4(a.x + b.x + d.x, a.y + b.y + d.y,
                           a.z + b.z + d.z, a.w + b.w + d.w);
    *(float4*)(g_lut + (size_t)c * DD + d4) = o;
}

// atom encoder: h0 = sum emb + vn0; also scatter h0 row into pooled
__global__ void k_encode_atoms(const int* __restrict__ x,
                               const float* __restrict__ atom_emb,
                               const float* __restrict__ vn_emb,
                               const int* __restrict__ batch,
                               float* __restrict__ out0) {
    int idx = blockIdx.x * blockDim.x + threadIdx.x;
    if (idx >= NN * 64) return;
    int n = idx >> 6;
    int d4 = (idx & 63) * 4;
    float4 acc = *(const float4*)(vn_emb + d4);
#pragma unroll
    for (int f = 0; f < 9; f++) {
        int v = __ldg(&x[n * 9 + f]);
        float4 e = *(const float4*)(atom_emb + ((size_t)(f * 120 + v) * DD + d4));
        acc.x += e.x; acc.y += e.y; acc.z += e.z; acc.w += e.w;
    }
    *(float4*)(out0 + (size_t)n * DD + d4) = acc;
    int g = __ldg(&batch[n]);
    red4(g_pooled + (size_t)g * DD + d4, acc.x, acc.y, acc.z, acc.w);
}

__global__ void k_vn_init(const float* __restrict__ vn_emb) {
    int i = blockIdx.x * blockDim.x + threadIdx.x;
    if (i < GG * DD) g_vn[i] = vn_emb[i & (DD - 1)];
}

__global__ void k_edge_msg(const int* __restrict__ ei,
                           const float* __restrict__ h) {
    int idx = blockIdx.x * blockDim.x + threadIdx.x;
    if (idx >= EE * 64) return;
    int e = idx >> 6;
    int d4 = (idx & 63) * 4;
    int s = __ldg(&ei[e]);
    int t = __ldg(&ei[EE + e]);
    int c = g_ecode[e];
    float4 hv = *(const float4*)(h + (size_t)s * DD + d4);
    float4 av = *(const float4*)(g_lut + (size_t)c * DD + d4);
    float m0 = fmaxf(hv.x + av.x, 0.f);
    float m1 = fmaxf(hv.y + av.y, 0.f);
    float m2 = fmaxf(hv.z + av.z, 0.f);
    float m3 = fmaxf(hv.w + av.w, 0.f);
    red4(g_agg + (size_t)t * DD + d4, m0, m1, m2, m3);
}

// ---------------- tensor-core GEMM: C[M,256] = op(A)[M,256] @ W[256,256] + bias
// 3-term bf16 split, W pre-split. Epilogue accumulates per-column sum/sumsq.
// MODE 1: A=(1+eps)h+agg.  MODE 2: A=relu(y*scale+shift).  MODE 3: A=A+A2.
#define BM 64
#define BK 32

__device__ __forceinline__ void mma_bf16(float* c, const uint32_t* a, uint32_t b0, uint32_t b1) {
    asm volatile(
        "mma.sync.aligned.m16n8k16.row.col.f32.bf16.bf16.f32 "
        "{%0,%1,%2,%3}, {%4,%5,%6,%7}, {%8,%9}, {%0,%1,%2,%3};"
        : "+f"(c[0]), "+f"(c[1]), "+f"(c[2]), "+f"(c[3])
        : "r"(a[0]), "r"(a[1]), "r"(a[2]), "r"(a[3]), "r"(b0), "r"(b1));
}

template <int MODE>
__global__ void __launch_bounds__(256, 2)
k_gemm_mma(const float* __restrict__ A, const float* __restrict__ A2,
           const float* __restrict__ epsp, const uint32_t* __restrict__ Whi,
           const uint32_t* __restrict__ Wlo, const float* __restrict__ bias,
           float* __restrict__ C, int M) {
    __shared__ uint32_t As_hi[BK / 2][72];
    __shared__ uint32_t As_lo[BK / 2][72];
    __shared__ uint32_t Bs_hi[BK / 2][264];
    __shared__ uint32_t Bs_lo[BK / 2][264];

    int tid = threadIdx.x;
    int lane = tid & 31;
    int wid = tid >> 5;
    int wr = wid >> 2;
    int wc = wid & 3;
    int row0 = blockIdx.x * BM;

    float e = 0.f;
    if (MODE == 1) e = 1.0f + __ldg(epsp);

    float acc[2][8][4];
#pragma unroll
    for (int i = 0; i < 2; i++)
#pragma unroll
        for (int j = 0; j < 8; j++)
#pragma unroll
            for (int r = 0; r < 4; r++) acc[i][j][r] = 0.f;

    for (int k0 = 0; k0 < DD; k0 += BK) {
        // ---- A tile: 64 rows x 32 k (fp32 -> bf16 hi/lo split) ----
#pragma unroll
        for (int q = 0; q < 2; q++) {
            int li = tid + q * 256;
            int r = li >> 3;
            int kk = (li & 7) * 4;
            float4 v = make_float4(0.f, 0.f, 0.f, 0.f);
            int gr = row0 + r;
            if (gr < M) {
                size_t off = (size_t)gr * DD + k0 + kk;
                if (MODE == 1) {
                    float4 hv = *(const float4*)(A + off);
                    float4 av = *(const float4*)(A2 + off);
                    v.x = e * hv.x + av.x; v.y = e * hv.y + av.y;
                    v.z = e * hv.z + av.z; v.w = e * hv.w + av.w;
                } else if (MODE == 2) {
                    float4 yv = *(const float4*)(A + off);
                    float4 sc = *(const float4*)(g_bnp + k0 + kk);
                    float4 sh = *(const float4*)(g_bnp + DD + k0 + kk);
                    v.x = fmaxf(yv.x * sc.x + sh.x, 0.f);
                    v.y = fmaxf(yv.y * sc.y + sh.y, 0.f);
                    v.z = fmaxf(yv.z * sc.z + sh.z, 0.f);
                    v.w = fmaxf(yv.w * sc.w + sh.w, 0.f);
                } else {  // MODE 3
                    float4 hv = *(const float4*)(A + off);
                    float4 av = *(const float4*)(A2 + off);
                    v.x = hv.x + av.x; v.y = hv.y + av.y;
                    v.z = hv.z + av.z; v.w = hv.w + av.w;
                }
            }
            int k2 = kk >> 1;
            uint32_t h0, l0, h1, l1;
            split_pack(v.x, v.y, h0, l0);
            split_pack(v.z, v.w, h1, l1);
            As_hi[k2][r] = h0;     As_lo[k2][r] = l0;
            As_hi[k2 + 1][r] = h1; As_lo[k2 + 1][r] = l1;
        }
        // ---- W tile: straight uint4 copies of pre-split weights ----
        {
            const uint32_t* wh = Whi + (size_t)(k0 >> 1) * DD;
            const uint32_t* wl = Wlo + (size_t)(k0 >> 1) * DD;
#pragma unroll
            for (int q = 0; q < 4; q++) {
                int li = tid + q * 256;
                int r = li >> 6;
                int n4 = (li & 63) * 4;
                *(uint4*)&Bs_hi[r][n4] = *(const uint4*)(wh + (size_t)r * DD + n4);
                *(uint4*)&Bs_lo[r][n4] = *(const uint4*)(wl + (size_t)r * DD + n4);
            }
        }
        __syncthreads();

#pragma unroll
        for (int s = 0; s < 2; s++) {
            int kb = s * 8 + (lane & 3);
            uint32_t ah[2][4], al[2][4];
#pragma unroll
            for (int i = 0; i < 2; i++) {
                int m = wr * 32 + i * 16 + (lane >> 2);
                ah[i][0] = As_hi[kb][m];     ah[i][1] = As_hi[kb][m + 8];
                ah[i][2] = As_hi[kb + 4][m]; ah[i][3] = As_hi[kb + 4][m + 8];
                al[i][0] = As_lo[kb][m];     al[i][1] = As_lo[kb][m + 8];
                al[i][2] = As_lo[kb + 4][m]; al[i][3] = As_lo[kb + 4][m + 8];
            }
#pragma unroll
            for (int j = 0; j < 8; j++) {
                int n = wc * 64 + j * 8 + (lane >> 2);
                uint32_t bh0 = Bs_hi[kb][n], bh1 = Bs_hi[kb + 4][n];
                uint32_t bl0 = Bs_lo[kb][n], bl1 = Bs_lo[kb + 4][n];
#pragma unroll
                for (int i = 0; i < 2; i++) {
                    mma_bf16(acc[i][j], ah[i], bh0, bh1);
                    mma_bf16(acc[i][j], ah[i], bl0, bl1);
                    mma_bf16(acc[i][j], al[i], bh0, bh1);
                }
            }
        }
        __syncthreads();
    }

    // ---- epilogue: += bias, store fp32, fused per-column sum/sumsq ----
#pragma unroll
    for (int j = 0; j < 8; j++) {
        int gc = wc * 64 + j * 8 + (lane & 3) * 2;
        float bx = __ldg(&bias[gc]);
        float by = __ldg(&bias[gc + 1]);
        float sx = 0.f, sy = 0.f, qx = 0.f, qy = 0.f;
#pragma unroll
        for (int i = 0; i < 2; i++) {
            int gr = row0 + wr * 32 + i * 16 + (lane >> 2);
            if (gr < M) {
                float2 v0 = make_float2(acc[i][j][0] + bx, acc[i][j][1] + by);
                *(float2*)(C + (size_t)gr * DD + gc) = v0;
                sx += v0.x; sy += v0.y; qx += v0.x * v0.x; qy += v0.y * v0.y;
            }
            if (gr + 8 < M) {
                float2 v1 = make_float2(acc[i][j][2] + bx, acc[i][j][3] + by);
                *(float2*)(C + (size_t)(gr + 8) * DD + gc) = v1;
                sx += v1.x; sy += v1.y; qx += v1.x * v1.x; qy += v1.y * v1.y;
            }
        }
#pragma unroll
        for (int d = 4; d < 32; d <<= 1) {
            sx += __shfl_xor_sync(0xffffffff, sx, d);
            sy += __shfl_xor_sync(0xffffffff, sy, d);
            qx += __shfl_xor_sync(0xffffffff, qx, d);
            qy += __shfl_xor_sync(0xffffffff, qy, d);
        }
        if ((lane >> 2) == 0) {
            red2(&g_stats[gc], sx, sy);
            red2(&g_stats[DD + gc], qx, qy);
        }
    }
}

// ---------------- BN prep: stats -> scale/shift, then zero stats ----------------
__global__ void k_bn_prep(const float* __restrict__ gamma, const float* __restrict__ beta,
                          float Minv) {
    int c = threadIdx.x;  // 256
    float m = g_stats[c] * Minv;
    float var = g_stats[DD + c] * Minv - m * m;
    float rs = rsqrtf(var + BN_EPS);
    float sc = gamma[c] * rs;
    g_bnp[c] = sc;
    g_bnp[DD + c] = beta[c] - m * sc;
    g_stats[c] = 0.f;
    g_stats[DD + c] = 0.f;
}

// BN apply (+relu, +vn[batch] gather, +pooled scatter of result row)
__global__ void k_bn_apply(const float* __restrict__ Yin, float* __restrict__ Yout,
                           const int* __restrict__ batch, int M,
                           int do_relu, int do_vn, int do_pool) {
    int idx = blockIdx.x * blockDim.x + threadIdx.x;
    if (idx >= M * 64) return;
    int r = idx >> 6;
    int c4 = (idx & 63) * 4;
    float4 sc = *(const float4*)(g_bnp + c4);
    float4 sh = *(const float4*)(g_bnp + DD + c4);
    float4 v = *(const float4*)(Yin + (size_t)r * DD + c4);
    v.x = v.x * sc.x + sh.x;
    v.y = v.y * sc.y + sh.y;
    v.z = v.z * sc.z + sh.z;
    v.w = v.w * sc.w + sh.w;
    if (do_relu) {
        v.x = fmaxf(v.x, 0.f); v.y = fmaxf(v.y, 0.f);
        v.z = fmaxf(v.z, 0.f); v.w = fmaxf(v.w, 0.f);
    }
    int g = 0;
    if (do_vn || do_pool) g = __ldg(&batch[r]);
    if (do_vn) {
        float4 w = *(const float4*)(g_vn + (size_t)g * DD + c4);
        v.x += w.x; v.y += w.y; v.z += w.z; v.w += w.w;
    }
    *(float4*)(Yout + (size_t)r * DD + c4) = v;
    if (do_pool) red4(g_pooled + (size_t)g * DD + c4, v.x, v.y, v.z, v.w);
}

// ---------------- host orchestration ----------------
extern "C" void kernel_launch(void* const* d_in, const int* in_sizes, int n_in,
                              void* d_out, int out_size) {
    const int* x          = (const int*)d_in[0];
    const int* edge_index = (const int*)d_in[1];
    const int* edge_attr  = (const int*)d_in[2];
    const int* batch      = (const int*)d_in[3];
    const float* atom_emb = (const float*)d_in[4];
    const float* bond_emb = (const float*)d_in[5];
    const float* vn_emb   = (const float*)d_in[6];
    const float* gin_eps  = (const float*)d_in[7];
    const float* conv_W1  = (const float*)d_in[8];
    const float* conv_b1  = (const float*)d_in[9];
    const float* conv_bn_g = (const float*)d_in[10];
    const float* conv_bn_b = (const float*)d_in[11];
    const float* conv_W2  = (const float*)d_in[12];
    const float* conv_b2  = (const float*)d_in[13];
    const float* outer_bn_g = (const float*)d_in[14];
    const float* outer_bn_b = (const float*)d_in[15];
    const float* vn_W1    = (const float*)d_in[16];
    const float* vn_b1    = (const float*)d_in[17];
    const float* vn_bn1_g = (const float*)d_in[18];
    const float* vn_bn1_b = (const float*)d_in[19];
    const float* vn_W2    = (const float*)d_in[20];
    const float* vn_b2    = (const float*)d_in[21];
    const float* vn_bn2_g = (const float*)d_in[22];
    const float* vn_bn2_b = (const float*)d_in[23];
    float* out = (float*)d_out;

    float *p_agg, *p_t, *p_y, *p_pooled, *p_vt, *p_vt2, *p_vn;
    uint32_t *p_whi, *p_wlo;
    cudaGetSymbolAddress((void**)&p_agg, g_agg);
    cudaGetSymbolAddress((void**)&p_t, g_t);
    cudaGetSymbolAddress((void**)&p_y, g_y);
    cudaGetSymbolAddress((void**)&p_pooled, g_pooled);
    cudaGetSymbolAddress((void**)&p_vt, g_vt);
    cudaGetSymbolAddress((void**)&p_vt2, g_vt2);
    cudaGetSymbolAddress((void**)&p_vn, g_vn);
    cudaGetSymbolAddress((void**)&p_whi, g_whi);
    cudaGetSymbolAddress((void**)&p_wlo, g_wlo);

    const size_t slot = (size_t)NN * DD;
    const size_t wslot = (size_t)128 * DD;
    const int blkN = (NN * 64 + 255) / 256;
    const int blkE = (EE * 64 + 255) / 256;
    const float invN = 1.0f / (float)NN;
    const float invG = 1.0f / (float)GG;

    // ---- prologue ----
    k_zero_stats<<<1, 512>>>();
    k_zero<<<(GG * 64 + 255) / 256, 256>>>(p_pooled, GG * 64);
    const int wgrid = (128 * DD + 255) / 256;
    for (int l = 0; l < LL; l++) {
        k_split_w<<<wgrid, 256>>>(conv_W1 + (size_t)l * DD * DD,
                                  p_whi + (size_t)l * wslot, p_wlo + (size_t)l * wslot);
        k_split_w<<<wgrid, 256>>>(conv_W2 + (size_t)l * DD * DD,
                                  p_whi + (size_t)(5 + l) * wslot, p_wlo + (size_t)(5 + l) * wslot);
    }
    for (int l = 0; l < LL - 1; l++) {
        k_split_w<<<wgrid, 256>>>(vn_W1 + (size_t)l * DD * DD,
                                  p_whi + (size_t)(10 + l) * wslot, p_wlo + (size_t)(10 + l) * wslot);
        k_split_w<<<wgrid, 256>>>(vn_W2 + (size_t)l * DD * DD,
                                  p_whi + (size_t)(14 + l) * wslot, p_wlo + (size_t)(14 + l) * wslot);
    }
    k_edge_code<<<(EE + 255) / 256, 256>>>(edge_attr);
    k_build_lut<<<(216 * 64 + 255) / 256, 256>>>(bond_emb);
    k_encode_atoms<<<blkN, 256>>>(x, atom_emb, vn_emb, batch, out);  // slot0 = h0+vn0, + pool
    k_vn_init<<<(GG * DD + 255) / 256, 256>>>(vn_emb);

    const int gBigM = (NN + BM - 1) / BM;
    const int gSmallM = (GG + BM - 1) / BM;

    for (int l = 0; l < LL; l++) {
        float* h = out + (size_t)l * slot;            // h_in^l (vn already added)
        float* z_out = out + (size_t)(l + 1) * slot;

        // edge message + scatter
        k_zero<<<(NN * 64 + 255) / 256, 256>>>(p_agg, NN * 64);
        k_edge_msg<<<blkE, 256>>>(edge_index, h);

        // virtual-node update (pooled_raw filled by previous layer's producer)
        if (l < LL - 1) {
            k_gemm_mma<3><<<gSmallM, 256>>>(p_pooled, p_vn, nullptr,
                                            p_whi + (size_t)(10 + l) * wslot,
                                            p_wlo + (size_t)(10 + l) * wslot,
                                            vn_b1 + l * DD, p_vt, GG);
            k_zero<<<(GG * 64 + 255) / 256, 256>>>(p_pooled, GG * 64);  // for next layer
            k_bn_prep<<<1, 256>>>(vn_bn1_g + l * DD, vn_bn1_b + l * DD, invG);
            k_gemm_mma<2><<<gSmallM, 256>>>(p_vt, nullptr, nullptr,
                                            p_whi + (size_t)(14 + l) * wslot,
                                            p_wlo + (size_t)(14 + l) * wslot,
                                            vn_b2 + l * DD, p_vt2, GG);
            k_bn_prep<<<1, 256>>>(vn_bn2_g + l * DD, vn_bn2_b + l * DD, invG);
            k_bn_apply<<<(GG * 64 + 255) / 256, 256>>>(p_vt2, p_vn, nullptr, GG, 1, 0, 0);
        }

        // GEMM1 fused gin_combine + stats
        k_gemm_mma<1><<<gBigM, 256>>>(h, p_agg, gin_eps + l,
                                      p_whi + (size_t)l * wslot, p_wlo + (size_t)l * wslot,
                                      conv_b1 + l * DD, p_y, NN);
        k_bn_prep<<<1, 256>>>(conv_bn_g + l * DD, conv_bn_b + l * DD, invN);
        // GEMM2 fused BN+ReLU on input + stats
        k_gemm_mma<2><<<gBigM, 256>>>(p_y, nullptr, nullptr,
                                      p_whi + (size_t)(5 + l) * wslot,
                                      p_wlo + (size_t)(5 + l) * wslot,
                                      conv_b2 + l * DD, p_t, NN);
        k_bn_prep<<<1, 256>>>(outer_bn_g + l * DD, outer_bn_b + l * DD, invN);
        // outer BN apply (+relu, +vn_new, +pool scatter for next layer) -> slot l+1
        int relu = (l < LL - 1) ? 1 : 0;
        int vnadd = (l < LL - 1) ? 1 : 0;
        int pool = (l < LL - 2) ? 1 : 0;   // next layer needs pooled only if it updates vn
        k_bn_apply<<<blkN, 256>>>(p_t, z_out, batch, NN, relu, vnadd, pool);
    }
}